// round 1
// baseline (speedup 1.0000x reference)
#include <cuda_runtime.h>
#include <math_constants.h>

#define BATCH 2
#define SEQ   2048
#define EMBED 1024
#define HEADS 16
#define HDIM  64
#define MROWS (BATCH * SEQ)   // 4096

// Scratch (alloc-free rule: __device__ globals)
__device__ float g_qkv[(size_t)MROWS * 3 * EMBED];   // [B*N, 3E]  50.3 MB
__device__ float g_attn[(size_t)MROWS * EMBED];      // [B*N, E]   16.8 MB

// ---------------------------------------------------------------------------
// C[M,N] = A[M,K] @ B[N,K]^T (+ bias), all row-major, dims multiples of 128/8.
// 128x128 block tile, BK=8, 256 threads, 8x8 register tile per thread.
// ---------------------------------------------------------------------------
__global__ __launch_bounds__(256) void gemm_nt(const float* __restrict__ A,
                                               const float* __restrict__ B,
                                               const float* __restrict__ bias,
                                               float* __restrict__ C,
                                               int M, int N, int K)
{
    __shared__ float As[8][128];
    __shared__ float Bs[8][128];

    const int t  = threadIdx.x;
    const int tx = t & 15;
    const int ty = t >> 4;
    const int m0 = blockIdx.y * 128;
    const int n0 = blockIdx.x * 128;

    const int lr = t >> 1;          // 0..127 : tile row loaded by this thread
    const int lk = (t & 1) * 4;     // 0 or 4 : k-quad

    const float* Ap = A + (size_t)(m0 + lr) * K + lk;
    const float* Bp = B + (size_t)(n0 + lr) * K + lk;

    float acc[8][8];
#pragma unroll
    for (int i = 0; i < 8; i++)
#pragma unroll
        for (int j = 0; j < 8; j++) acc[i][j] = 0.f;

    for (int k0 = 0; k0 < K; k0 += 8) {
        float4 av = *reinterpret_cast<const float4*>(Ap + k0);
        float4 bv = *reinterpret_cast<const float4*>(Bp + k0);
        __syncthreads();
        As[lk + 0][lr] = av.x; As[lk + 1][lr] = av.y;
        As[lk + 2][lr] = av.z; As[lk + 3][lr] = av.w;
        Bs[lk + 0][lr] = bv.x; Bs[lk + 1][lr] = bv.y;
        Bs[lk + 2][lr] = bv.z; Bs[lk + 3][lr] = bv.w;
        __syncthreads();
#pragma unroll
        for (int k = 0; k < 8; k++) {
            float4 a0 = *reinterpret_cast<const float4*>(&As[k][ty * 8]);
            float4 a1 = *reinterpret_cast<const float4*>(&As[k][ty * 8 + 4]);
            float4 b0 = *reinterpret_cast<const float4*>(&Bs[k][tx * 8]);
            float4 b1 = *reinterpret_cast<const float4*>(&Bs[k][tx * 8 + 4]);
            float ar[8] = {a0.x, a0.y, a0.z, a0.w, a1.x, a1.y, a1.z, a1.w};
            float br[8] = {b0.x, b0.y, b0.z, b0.w, b1.x, b1.y, b1.z, b1.w};
#pragma unroll
            for (int i = 0; i < 8; i++)
#pragma unroll
                for (int j = 0; j < 8; j++)
                    acc[i][j] += ar[i] * br[j];
        }
    }

    float4 bb0 = make_float4(0.f, 0.f, 0.f, 0.f);
    float4 bb1 = make_float4(0.f, 0.f, 0.f, 0.f);
    if (bias) {
        bb0 = *reinterpret_cast<const float4*>(bias + n0 + tx * 8);
        bb1 = *reinterpret_cast<const float4*>(bias + n0 + tx * 8 + 4);
    }
#pragma unroll
    for (int i = 0; i < 8; i++) {
        const int row = m0 + ty * 8 + i;
        float4 o0, o1;
        o0.x = acc[i][0] + bb0.x; o0.y = acc[i][1] + bb0.y;
        o0.z = acc[i][2] + bb0.z; o0.w = acc[i][3] + bb0.w;
        o1.x = acc[i][4] + bb1.x; o1.y = acc[i][5] + bb1.y;
        o1.z = acc[i][6] + bb1.z; o1.w = acc[i][7] + bb1.w;
        *reinterpret_cast<float4*>(C + (size_t)row * N + n0 + tx * 8)     = o0;
        *reinterpret_cast<float4*>(C + (size_t)row * N + n0 + tx * 8 + 4) = o1;
    }
}

// ---------------------------------------------------------------------------
// Fused flash attention, fp32. One block = one (b,h) and 64 query rows.
// Key/value tiles of 32. 256 threads (16x16): thread owns 4 q-rows;
// scores: 2 key-cols each; output: 4 d-cols each. Online softmax in regs,
// row stats reduced across the 16 tx lanes via shfl.
// ---------------------------------------------------------------------------
__global__ __launch_bounds__(256) void attn_kernel(const float* __restrict__ qkv,
                                                   float* __restrict__ out)
{
    __shared__ float Qs[64][64];      // [r][d] (pre-scaled by 1/sqrt(D))
    __shared__ float Ks[64][33];      // [d][c] padded (2-way max on store)
    __shared__ float Vs[32][64];      // [c][d]
    __shared__ float Ps[64][33];      // [r][c] padded

    const int t  = threadIdx.x;
    const int tx = t & 15;
    const int ty = t >> 4;
    const int bh = blockIdx.y;
    const int b  = bh >> 4;           // / HEADS
    const int h  = bh & 15;           // % HEADS
    const int n0 = blockIdx.x * 64;

    const float* base = qkv + (size_t)b * SEQ * (3 * EMBED);
    const int qoff = h * HDIM;
    const int koff = EMBED + h * HDIM;
    const int voff = 2 * EMBED + h * HDIM;

    // Load Q tile (64 rows x 16 quads), scale by 1/8 once.
    for (int e = t; e < 64 * 16; e += 256) {
        const int r  = e >> 4;
        const int dq = (e & 15) << 2;
        float4 v = *reinterpret_cast<const float4*>(
            base + (size_t)(n0 + r) * (3 * EMBED) + qoff + dq);
        v.x *= 0.125f; v.y *= 0.125f; v.z *= 0.125f; v.w *= 0.125f;
        *reinterpret_cast<float4*>(&Qs[r][dq]) = v;
    }

    float m_i[4], l_i[4], accO[4][4];
#pragma unroll
    for (int i = 0; i < 4; i++) {
        m_i[i] = -CUDART_INF_F;
        l_i[i] = 0.f;
#pragma unroll
        for (int j = 0; j < 4; j++) accO[i][j] = 0.f;
    }

    const int r0 = ty * 4;
    const int cc = tx * 2;
    const int d0 = tx * 4;

    for (int c0 = 0; c0 < SEQ; c0 += 32) {
        __syncthreads();   // protect prev-iter Ks/Vs/Ps readers
        // Load K (transposed, padded) and V (straight) tiles: 32 rows x 16 quads
        for (int e = t; e < 32 * 16; e += 256) {
            const int c  = e >> 4;
            const int dq = (e & 15) << 2;
            const float* rowp = base + (size_t)(c0 + c) * (3 * EMBED);
            float4 kv = *reinterpret_cast<const float4*>(rowp + koff + dq);
            Ks[dq + 0][c] = kv.x; Ks[dq + 1][c] = kv.y;
            Ks[dq + 2][c] = kv.z; Ks[dq + 3][c] = kv.w;
            float4 vv = *reinterpret_cast<const float4*>(rowp + voff + dq);
            *reinterpret_cast<float4*>(&Vs[c][dq]) = vv;
        }
        __syncthreads();

        // Scores: s[i][j] for rows r0+i, cols cc+j
        float s[4][2];
#pragma unroll
        for (int i = 0; i < 4; i++) { s[i][0] = 0.f; s[i][1] = 0.f; }
#pragma unroll 16
        for (int d = 0; d < HDIM; d++) {
            const float k0v = Ks[d][cc];
            const float k1v = Ks[d][cc + 1];
#pragma unroll
            for (int i = 0; i < 4; i++) {
                const float q = Qs[r0 + i][d];
                s[i][0] += q * k0v;
                s[i][1] += q * k1v;
            }
        }

        // Online softmax per row (reduce across 16 tx lanes; xor masks < 16
        // keep partners in the same ty group)
#pragma unroll
        for (int i = 0; i < 4; i++) {
            float mx = fmaxf(s[i][0], s[i][1]);
#pragma unroll
            for (int off = 8; off; off >>= 1)
                mx = fmaxf(mx, __shfl_xor_sync(0xffffffffu, mx, off));
            const float mnew = fmaxf(m_i[i], mx);
            const float corr = __expf(m_i[i] - mnew);
            const float p0 = __expf(s[i][0] - mnew);
            const float p1 = __expf(s[i][1] - mnew);
            float ls = p0 + p1;
#pragma unroll
            for (int off = 8; off; off >>= 1)
                ls += __shfl_xor_sync(0xffffffffu, ls, off);
            m_i[i] = mnew;
            l_i[i] = l_i[i] * corr + ls;
#pragma unroll
            for (int j = 0; j < 4; j++) accO[i][j] *= corr;
            Ps[r0 + i][cc]     = p0;
            Ps[r0 + i][cc + 1] = p1;
        }
        __syncthreads();

        // accO += P @ V   (P broadcast along tx, V float4 per d-quad)
#pragma unroll 8
        for (int c = 0; c < 32; c++) {
            const float4 v = *reinterpret_cast<const float4*>(&Vs[c][d0]);
#pragma unroll
            for (int i = 0; i < 4; i++) {
                const float p = Ps[r0 + i][c];
                accO[i][0] += p * v.x;
                accO[i][1] += p * v.y;
                accO[i][2] += p * v.z;
                accO[i][3] += p * v.w;
            }
        }
    }

    // Normalize and write [B, N, E]
    float* obase = out + (size_t)b * SEQ * EMBED;
#pragma unroll
    for (int i = 0; i < 4; i++) {
        const float inv = 1.f / l_i[i];
        float4 o;
        o.x = accO[i][0] * inv; o.y = accO[i][1] * inv;
        o.z = accO[i][2] * inv; o.w = accO[i][3] * inv;
        *reinterpret_cast<float4*>(
            obase + (size_t)(n0 + r0 + i) * EMBED + h * HDIM + d0) = o;
    }
}

// ---------------------------------------------------------------------------
extern "C" void kernel_launch(void* const* d_in, const int* in_sizes, int n_in,
                              void* d_out, int out_size)
{
    const float* x      = (const float*)d_in[0];
    const float* w_qkv  = (const float*)d_in[1];
    const float* w_proj = (const float*)d_in[2];
    const float* b_proj = (const float*)d_in[3];
    float* out = (float*)d_out;

    float* qkv_ptr = nullptr;
    float* attn_ptr = nullptr;
    cudaGetSymbolAddress((void**)&qkv_ptr, g_qkv);
    cudaGetSymbolAddress((void**)&attn_ptr, g_attn);

    // 1) qkv = x @ w_qkv^T : [4096,1024] x [3072,1024]^T -> [4096,3072]
    gemm_nt<<<dim3(3 * EMBED / 128, MROWS / 128), 256>>>(
        x, w_qkv, nullptr, qkv_ptr, MROWS, 3 * EMBED, EMBED);

    // 2) fused attention -> g_attn [4096,1024]
    attn_kernel<<<dim3(SEQ / 64, BATCH * HEADS), 256>>>(qkv_ptr, attn_ptr);

    // 3) out = attn @ w_proj^T + b : [4096,1024] x [1024,1024]^T
    gemm_nt<<<dim3(EMBED / 128, MROWS / 128), 256>>>(
        attn_ptr, w_proj, b_proj, out, MROWS, EMBED, EMBED);
}

// round 3
// speedup vs baseline: 2.8860x; 2.8860x over previous
#include <cuda_runtime.h>
#include <cuda_bf16.h>
#include <math_constants.h>
#include <cstdint>

#define BATCH 2
#define SEQ   2048
#define EMBED 1024
#define HEADS 16
#define HDIM  64
#define MROWS (BATCH * SEQ)   // 4096

// Scratch (alloc-free rule: __device__ globals)
__device__ float g_qkv[(size_t)MROWS * 3 * EMBED];   // [B*N, 3E]
__device__ float g_attn[(size_t)MROWS * EMBED];      // [B*N, E]

// ---------------------------------------------------------------------------
// helpers
// ---------------------------------------------------------------------------
static __device__ __forceinline__ uint32_t smem_u32(const void* p) {
    return (uint32_t)__cvta_generic_to_shared(p);
}

static __device__ __forceinline__ void ldsm4(uint32_t& r0, uint32_t& r1,
                                             uint32_t& r2, uint32_t& r3,
                                             uint32_t addr) {
    asm volatile("ldmatrix.sync.aligned.m8n8.x4.shared.b16 {%0,%1,%2,%3},[%4];\n"
                 : "=r"(r0), "=r"(r1), "=r"(r2), "=r"(r3) : "r"(addr));
}

static __device__ __forceinline__ void ldsm4t(uint32_t& r0, uint32_t& r1,
                                              uint32_t& r2, uint32_t& r3,
                                              uint32_t addr) {
    asm volatile("ldmatrix.sync.aligned.m8n8.x4.trans.shared.b16 {%0,%1,%2,%3},[%4];\n"
                 : "=r"(r0), "=r"(r1), "=r"(r2), "=r"(r3) : "r"(addr));
}

static __device__ __forceinline__ void mma16816(float c[4],
                                                uint32_t a0, uint32_t a1,
                                                uint32_t a2, uint32_t a3,
                                                uint32_t b0, uint32_t b1) {
    asm volatile(
        "mma.sync.aligned.m16n8k16.row.col.f32.bf16.bf16.f32 "
        "{%0,%1,%2,%3},{%4,%5,%6,%7},{%8,%9},{%0,%1,%2,%3};\n"
        : "+f"(c[0]), "+f"(c[1]), "+f"(c[2]), "+f"(c[3])
        : "r"(a0), "r"(a1), "r"(a2), "r"(a3), "r"(b0), "r"(b1));
}

// split fp32 -> (hi, lo) bf16 pair, packed two-at-a-time into b32 regs
static __device__ __forceinline__ void split_pack2(float a, float b,
                                                   uint32_t& hi, uint32_t& lo) {
    __nv_bfloat16 ha = __float2bfloat16_rn(a);
    __nv_bfloat16 hb = __float2bfloat16_rn(b);
    __nv_bfloat16 la = __float2bfloat16_rn(a - __bfloat162float(ha));
    __nv_bfloat16 lb = __float2bfloat16_rn(b - __bfloat162float(hb));
    __nv_bfloat162 H; H.x = ha; H.y = hb;
    __nv_bfloat162 L; L.x = la; L.y = lb;
    hi = reinterpret_cast<uint32_t&>(H);
    lo = reinterpret_cast<uint32_t&>(L);
}

// split 4 contiguous floats, store hi/lo (2 packed b32 each) to smem row
static __device__ __forceinline__ void split_store4(float4 v,
                                                    __nv_bfloat16* hrow,
                                                    __nv_bfloat16* lrow) {
    uint32_t h0, l0, h1, l1;
    split_pack2(v.x, v.y, h0, l0);
    split_pack2(v.z, v.w, h1, l1);
    reinterpret_cast<uint32_t*>(hrow)[0] = h0;
    reinterpret_cast<uint32_t*>(hrow)[1] = h1;
    reinterpret_cast<uint32_t*>(lrow)[0] = l0;
    reinterpret_cast<uint32_t*>(lrow)[1] = l1;
}

// ---------------------------------------------------------------------------
// C[M,N] = A[M,K] @ B[N,K]^T (+bias), bf16 3-term split via mma.sync.
// 128x128 block, BK=16, 256 threads = 8 warps in 2(m) x 4(n), warp tile 64x32.
// ---------------------------------------------------------------------------
#define GBK  16
#define APAD 24   // row stride pad: conflict-free ldmatrix

__global__ __launch_bounds__(256) void gemm_nt_mma(const float* __restrict__ A,
                                                   const float* __restrict__ B,
                                                   const float* __restrict__ bias,
                                                   float* __restrict__ C,
                                                   int M, int N, int K)
{
    __shared__ __nv_bfloat16 Ah[128][APAD], Al[128][APAD];
    __shared__ __nv_bfloat16 Bh[128][APAD], Bl[128][APAD];

    const int t    = threadIdx.x;
    const int lane = t & 31;
    const int warp = t >> 5;
    const int wm   = warp >> 2;   // 0..1
    const int wn   = warp & 3;    // 0..3
    const int m0   = blockIdx.y * 128;
    const int n0   = blockIdx.x * 128;

    float acc[4][4][4];
#pragma unroll
    for (int i = 0; i < 4; i++)
#pragma unroll
        for (int j = 0; j < 4; j++)
#pragma unroll
            for (int r = 0; r < 4; r++) acc[i][j][r] = 0.f;

    const int lr = t >> 1;            // 0..127
    const int lc = (t & 1) * 8;       // 0 or 8
    const float* Ap = A + (size_t)(m0 + lr) * K + lc;
    const float* Bp = B + (size_t)(n0 + lr) * K + lc;

    // precomputed ldmatrix smem offsets
    const int a_row = (lane & 15);
    const int a_col = (lane >> 4) * 8;
    const int b_row = (lane >> 4) * 8 + (lane & 7);
    const int b_col = ((lane >> 3) & 1) * 8;

    for (int k0 = 0; k0 < K; k0 += GBK) {
        float4 av0 = *reinterpret_cast<const float4*>(Ap + k0);
        float4 av1 = *reinterpret_cast<const float4*>(Ap + k0 + 4);
        float4 bv0 = *reinterpret_cast<const float4*>(Bp + k0);
        float4 bv1 = *reinterpret_cast<const float4*>(Bp + k0 + 4);
        __syncthreads();
        split_store4(av0, &Ah[lr][lc],     &Al[lr][lc]);
        split_store4(av1, &Ah[lr][lc + 4], &Al[lr][lc + 4]);
        split_store4(bv0, &Bh[lr][lc],     &Bl[lr][lc]);
        split_store4(bv1, &Bh[lr][lc + 4], &Bl[lr][lc + 4]);
        __syncthreads();

        uint32_t ah[4][4], al[4][4], bh[4][2], bl[4][2];
#pragma unroll
        for (int mi = 0; mi < 4; mi++) {
            const int row = wm * 64 + mi * 16 + a_row;
            ldsm4(ah[mi][0], ah[mi][1], ah[mi][2], ah[mi][3],
                  smem_u32(&Ah[row][a_col]));
            ldsm4(al[mi][0], al[mi][1], al[mi][2], al[mi][3],
                  smem_u32(&Al[row][a_col]));
        }
#pragma unroll
        for (int gn = 0; gn < 2; gn++) {
            const int row = wn * 32 + gn * 16 + b_row;
            ldsm4(bh[2 * gn][0], bh[2 * gn][1], bh[2 * gn + 1][0], bh[2 * gn + 1][1],
                  smem_u32(&Bh[row][b_col]));
            ldsm4(bl[2 * gn][0], bl[2 * gn][1], bl[2 * gn + 1][0], bl[2 * gn + 1][1],
                  smem_u32(&Bl[row][b_col]));
        }
#pragma unroll
        for (int mi = 0; mi < 4; mi++)
#pragma unroll
            for (int ni = 0; ni < 4; ni++) {
                mma16816(acc[mi][ni], ah[mi][0], ah[mi][1], ah[mi][2], ah[mi][3],
                         bh[ni][0], bh[ni][1]);
                mma16816(acc[mi][ni], ah[mi][0], ah[mi][1], ah[mi][2], ah[mi][3],
                         bl[ni][0], bl[ni][1]);
                mma16816(acc[mi][ni], al[mi][0], al[mi][1], al[mi][2], al[mi][3],
                         bh[ni][0], bh[ni][1]);
            }
    }

    const int g  = lane >> 2;
    const int t4 = lane & 3;
#pragma unroll
    for (int mi = 0; mi < 4; mi++)
#pragma unroll
        for (int ni = 0; ni < 4; ni++) {
            const int row = m0 + wm * 64 + mi * 16 + g;
            const int col = n0 + wn * 32 + ni * 8 + t4 * 2;
            float b0v = 0.f, b1v = 0.f;
            if (bias) { b0v = bias[col]; b1v = bias[col + 1]; }
            float2 w0 = make_float2(acc[mi][ni][0] + b0v, acc[mi][ni][1] + b1v);
            float2 w1 = make_float2(acc[mi][ni][2] + b0v, acc[mi][ni][3] + b1v);
            *reinterpret_cast<float2*>(C + (size_t)row * N + col)       = w0;
            *reinterpret_cast<float2*>(C + (size_t)(row + 8) * N + col) = w1;
        }
}

// ---------------------------------------------------------------------------
// Fused flash attention with bf16 3-term mma. One block = one (b,h), 64 q rows.
// 4 warps (16 q rows each), K/V tiles of 32 columns.
// ---------------------------------------------------------------------------
#define QPAD 72   // 144B row stride: conflict-free ldmatrix (incl. trans)

__global__ __launch_bounds__(128) void attn_mma(const float* __restrict__ qkv,
                                                float* __restrict__ out)
{
    __shared__ __nv_bfloat16 Qh[64][QPAD], Ql[64][QPAD];
    __shared__ __nv_bfloat16 Kh[32][QPAD], Kl[32][QPAD];
    __shared__ __nv_bfloat16 Vh[32][QPAD], Vl[32][QPAD];

    const int t    = threadIdx.x;
    const int lane = t & 31;
    const int warp = t >> 5;
    const int bh_  = blockIdx.y;
    const int b    = bh_ >> 4;
    const int h    = bh_ & 15;
    const int n0   = blockIdx.x * 64;

    const float* base = qkv + (size_t)b * SEQ * (3 * EMBED);
    const int qoff = h * HDIM;
    const int koff = EMBED + h * HDIM;
    const int voff = 2 * EMBED + h * HDIM;

    // Load + split Q tile (64 x 64), pre-scaled by 1/sqrt(D) = 1/8
#pragma unroll
    for (int i = 0; i < 8; i++) {
        const int idx = t + i * 128;
        const int r = idx >> 4;
        const int q = (idx & 15) * 4;
        float4 v = *reinterpret_cast<const float4*>(
            base + (size_t)(n0 + r) * (3 * EMBED) + qoff + q);
        v.x *= 0.125f; v.y *= 0.125f; v.z *= 0.125f; v.w *= 0.125f;
        split_store4(v, &Qh[r][q], &Ql[r][q]);
    }

    float m0r = -CUDART_INF_F, m1r = -CUDART_INF_F;
    float l0r = 0.f, l1r = 0.f;
    float o[8][4];
#pragma unroll
    for (int i = 0; i < 8; i++)
#pragma unroll
        for (int j = 0; j < 4; j++) o[i][j] = 0.f;

    const int g  = lane >> 2;

    const int a_row = warp * 16 + (lane & 15);
    const int a_colbase = (lane >> 4) * 8;
    const int b_row = (lane >> 4) * 8 + (lane & 7);
    const int b_colk = ((lane >> 3) & 1) * 8;
    const int v_rowk = ((lane >> 3) & 1) * 8 + (lane & 7);
    const int v_col  = (lane >> 4) * 8;

    for (int c0 = 0; c0 < SEQ; c0 += 32) {
        __syncthreads();
        // load + split K and V tiles (32 x 64 each)
#pragma unroll
        for (int i = 0; i < 4; i++) {
            const int idx = t + i * 128;
            const int r = idx >> 4;
            const int q = (idx & 15) * 4;
            const float* rp = base + (size_t)(c0 + r) * (3 * EMBED);
            float4 kv = *reinterpret_cast<const float4*>(rp + koff + q);
            split_store4(kv, &Kh[r][q], &Kl[r][q]);
            float4 vv = *reinterpret_cast<const float4*>(rp + voff + q);
            split_store4(vv, &Vh[r][q], &Vl[r][q]);
        }
        __syncthreads();

        // ---- S = Q K^T  (16 rows x 32 cols per warp) ----
        float s[4][4];
#pragma unroll
        for (int i = 0; i < 4; i++)
#pragma unroll
            for (int j = 0; j < 4; j++) s[i][j] = 0.f;

#pragma unroll
        for (int ks = 0; ks < 4; ks++) {
            uint32_t qh[4], ql[4], kh[4][2], kl[4][2];
            const int acol = ks * 16 + a_colbase;
            ldsm4(qh[0], qh[1], qh[2], qh[3], smem_u32(&Qh[a_row][acol]));
            ldsm4(ql[0], ql[1], ql[2], ql[3], smem_u32(&Ql[a_row][acol]));
            const int kcol = ks * 16 + b_colk;
#pragma unroll
            for (int gn = 0; gn < 2; gn++) {
                const int row = gn * 16 + b_row;
                ldsm4(kh[2 * gn][0], kh[2 * gn][1], kh[2 * gn + 1][0], kh[2 * gn + 1][1],
                      smem_u32(&Kh[row][kcol]));
                ldsm4(kl[2 * gn][0], kl[2 * gn][1], kl[2 * gn + 1][0], kl[2 * gn + 1][1],
                      smem_u32(&Kl[row][kcol]));
            }
#pragma unroll
            for (int ni = 0; ni < 4; ni++) {
                mma16816(s[ni], qh[0], qh[1], qh[2], qh[3], kh[ni][0], kh[ni][1]);
                mma16816(s[ni], qh[0], qh[1], qh[2], qh[3], kl[ni][0], kl[ni][1]);
                mma16816(s[ni], ql[0], ql[1], ql[2], ql[3], kh[ni][0], kh[ni][1]);
            }
        }

        // ---- online softmax (rows g and g+8 of this warp's 16) ----
        float mx0 = s[0][0], mx1 = s[0][2];
#pragma unroll
        for (int ni = 0; ni < 4; ni++) {
            mx0 = fmaxf(mx0, fmaxf(s[ni][0], s[ni][1]));
            mx1 = fmaxf(mx1, fmaxf(s[ni][2], s[ni][3]));
        }
        mx0 = fmaxf(mx0, __shfl_xor_sync(0xffffffffu, mx0, 1));
        mx0 = fmaxf(mx0, __shfl_xor_sync(0xffffffffu, mx0, 2));
        mx1 = fmaxf(mx1, __shfl_xor_sync(0xffffffffu, mx1, 1));
        mx1 = fmaxf(mx1, __shfl_xor_sync(0xffffffffu, mx1, 2));

        const float mn0 = fmaxf(m0r, mx0);
        const float mn1 = fmaxf(m1r, mx1);
        const float cor0 = __expf(m0r - mn0);
        const float cor1 = __expf(m1r - mn1);
        float sum0 = 0.f, sum1 = 0.f;
#pragma unroll
        for (int ni = 0; ni < 4; ni++) {
            s[ni][0] = __expf(s[ni][0] - mn0); sum0 += s[ni][0];
            s[ni][1] = __expf(s[ni][1] - mn0); sum0 += s[ni][1];
            s[ni][2] = __expf(s[ni][2] - mn1); sum1 += s[ni][2];
            s[ni][3] = __expf(s[ni][3] - mn1); sum1 += s[ni][3];
        }
        sum0 += __shfl_xor_sync(0xffffffffu, sum0, 1);
        sum0 += __shfl_xor_sync(0xffffffffu, sum0, 2);
        sum1 += __shfl_xor_sync(0xffffffffu, sum1, 1);
        sum1 += __shfl_xor_sync(0xffffffffu, sum1, 2);
        m0r = mn0; m1r = mn1;
        l0r = l0r * cor0 + sum0;
        l1r = l1r * cor1 + sum1;
#pragma unroll
        for (int ni = 0; ni < 8; ni++) {
            o[ni][0] *= cor0; o[ni][1] *= cor0;
            o[ni][2] *= cor1; o[ni][3] *= cor1;
        }

        // ---- pack P (hi/lo) as mma A operands ----
        uint32_t pah[2][4], pal[2][4];
#pragma unroll
        for (int ks2 = 0; ks2 < 2; ks2++) {
            const int f0 = 2 * ks2, f1 = 2 * ks2 + 1;
            split_pack2(s[f0][0], s[f0][1], pah[ks2][0], pal[ks2][0]);
            split_pack2(s[f0][2], s[f0][3], pah[ks2][1], pal[ks2][1]);
            split_pack2(s[f1][0], s[f1][1], pah[ks2][2], pal[ks2][2]);
            split_pack2(s[f1][2], s[f1][3], pah[ks2][3], pal[ks2][3]);
        }

        // ---- O += P V ----
#pragma unroll
        for (int ks2 = 0; ks2 < 2; ks2++) {
            uint32_t vh[8][2], vl[8][2];
            const int rr = ks2 * 16 + v_rowk;
#pragma unroll
            for (int gn = 0; gn < 4; gn++) {
                const int cc = gn * 16 + v_col;
                ldsm4t(vh[2 * gn][0], vh[2 * gn][1], vh[2 * gn + 1][0], vh[2 * gn + 1][1],
                       smem_u32(&Vh[rr][cc]));
                ldsm4t(vl[2 * gn][0], vl[2 * gn][1], vl[2 * gn + 1][0], vl[2 * gn + 1][1],
                       smem_u32(&Vl[rr][cc]));
            }
#pragma unroll
            for (int ni = 0; ni < 8; ni++) {
                mma16816(o[ni], pah[ks2][0], pah[ks2][1], pah[ks2][2], pah[ks2][3],
                         vh[ni][0], vh[ni][1]);
                mma16816(o[ni], pah[ks2][0], pah[ks2][1], pah[ks2][2], pah[ks2][3],
                         vl[ni][0], vl[ni][1]);
                mma16816(o[ni], pal[ks2][0], pal[ks2][1], pal[ks2][2], pal[ks2][3],
                         vh[ni][0], vh[ni][1]);
            }
        }
    }

    // ---- normalize + write [B, N, E] ----
    const float inv0 = 1.f / l0r;
    const float inv1 = 1.f / l1r;
    float* ob = out + (size_t)b * SEQ * EMBED;
    const int row = n0 + warp * 16 + g;
    const int colb = h * HDIM + (lane & 3) * 2;
#pragma unroll
    for (int ni = 0; ni < 8; ni++) {
        const int col = colb + ni * 8;
        float2 w0 = make_float2(o[ni][0] * inv0, o[ni][1] * inv0);
        float2 w1 = make_float2(o[ni][2] * inv1, o[ni][3] * inv1);
        *reinterpret_cast<float2*>(ob + (size_t)row * EMBED + col)       = w0;
        *reinterpret_cast<float2*>(ob + (size_t)(row + 8) * EMBED + col) = w1;
    }
}

// ---------------------------------------------------------------------------
extern "C" void kernel_launch(void* const* d_in, const int* in_sizes, int n_in,
                              void* d_out, int out_size)
{
    const float* x      = (const float*)d_in[0];
    const float* w_qkv  = (const float*)d_in[1];
    const float* w_proj = (const float*)d_in[2];
    const float* b_proj = (const float*)d_in[3];
    float* out = (float*)d_out;

    float* qkv_ptr = nullptr;
    float* attn_ptr = nullptr;
    cudaGetSymbolAddress((void**)&qkv_ptr, g_qkv);
    cudaGetSymbolAddress((void**)&attn_ptr, g_attn);

    // 1) qkv = x @ w_qkv^T : [4096,1024] x [3072,1024]^T
    gemm_nt_mma<<<dim3(3 * EMBED / 128, MROWS / 128), 256>>>(
        x, w_qkv, nullptr, qkv_ptr, MROWS, 3 * EMBED, EMBED);

    // 2) fused attention -> g_attn [4096,1024]
    attn_mma<<<dim3(SEQ / 64, BATCH * HEADS), 128>>>(qkv_ptr, attn_ptr);

    // 3) out = attn @ w_proj^T + b
    gemm_nt_mma<<<dim3(EMBED / 128, MROWS / 128), 256>>>(
        attn_ptr, w_proj, b_proj, out, MROWS, EMBED, EMBED);
}